// round 15
// baseline (speedup 1.0000x reference)
#include <cuda_runtime.h>
#include <math.h>

// Fixed shapes
#define BB     4
#define NN     16384
#define MM     1024
#define CC     64          // feature channels
#define COP    64          // NeighborOperator out channels
#define COUT   128         // final out channels
#define KK     32          // neighbors
#define R2     0.25f
#define NCHUNK 17          // float4 chunks per row: [feat(64) | rel(3) | pad]
// Row layout (68 floats): [feat(64) | rel(3) | 0]. W_op rows reordered to match:
//   W_op row j<3 (rel)   -> slot 64+j
//   W_op row j>=3 (feat) -> slot j-3

__global__ __launch_bounds__(128, 5)
void pointnet_sampler_kernel(
    const float* __restrict__ positions,   // (B, N, 3)
    const float* __restrict__ features,    // (B, N, 64)
    const float* __restrict__ centers,     // (B, M, 3)
    const float* __restrict__ distances,   // (B, M, N)
    const float* __restrict__ W_op,        // (67, 64)
    const float* __restrict__ b_op,        // (64,)
    const float* __restrict__ W_agg,       // (64, 128)
    const float* __restrict__ b_agg,       // (128,)
    float* __restrict__ out)               // (B, M, 128)
{
    const int bm2  = blockIdx.x;           // 0 .. B*M/2-1 : handles centers 2*bm2, 2*bm2+1
    const int m0   = bm2 << 1;             // first center (global index over B*M)
    const int b    = bm2 >> 9;             // batch (both centers share it: M even)
    const int tid  = threadIdx.x;
    const int lane = tid & 31;
    const int wid  = tid >> 5;
    const int kt   = tid & 7;              // k-lane: rows kt, kt+8, kt+16, kt+24
    const int ct   = tid >> 3;             // channel tile: 4ct .. 4ct+3
    const int c0   = ct << 2;

    __shared__ unsigned s_mask[2][8];
    __shared__ int      s_idx[2][KK];
    __shared__ int      s_count[2];
    __shared__ __align__(16) float4 s_in4[2][KK][NCHUNK];  // 17.4 KB
    __shared__ __align__(16) float4 s_w4[COP][NCHUNK];     // 17.4 KB
    __shared__ float    s_pool[2][COP];

    // ---- Phase A: predicate first 256 distances of BOTH centers in one round trip ----
    {
        const float* d0 = distances + (size_t)m0 * NN;
        const float* d1 = d0 + NN;
        const unsigned ma = __ballot_sync(0xffffffffu, d0[tid]       < R2);
        const unsigned mb = __ballot_sync(0xffffffffu, d0[tid + 128] < R2);
        const unsigned mc = __ballot_sync(0xffffffffu, d1[tid]       < R2);
        const unsigned md = __ballot_sync(0xffffffffu, d1[tid + 128] < R2);
        if (lane == 0) {
            s_mask[0][wid]     = ma;  s_mask[0][4 + wid] = mb;
            s_mask[1][wid]     = mc;  s_mask[1][4 + wid] = md;
        }
    }
    __syncthreads();

    // ---- Phase B: warps 0,1 extract first-K indices (center wid); all warps stage W ----
    if (wid < 2) {
        int cnt = 0;
        #pragma unroll
        for (int mm = 0; mm < 8; mm++) {
            const unsigned m = s_mask[wid][mm];
            const bool pred = (m >> lane) & 1u;
            const int rank = cnt + __popc(m & ((1u << lane) - 1u));
            if (pred && rank < KK) s_idx[wid][rank] = mm * 32 + lane;
            cnt += __popc(m);
        }
        // Rare fallback (~1e-6 per row): continue scan past 256 in original order.
        const float* drow = distances + (size_t)(m0 + wid) * NN;
        for (int j0 = 256; j0 < NN && cnt < KK; j0 += 32) {
            const bool pred = drow[j0 + lane] < R2;
            const unsigned m = __ballot_sync(0xffffffffu, pred);
            if (pred) {
                const int rank = cnt + __popc(m & ((1u << lane) - 1u));
                if (rank < KK) s_idx[wid][rank] = j0 + lane;
            }
            cnt += __popc(m);
        }
        if (lane == 0) s_count[wid] = (cnt > KK) ? KK : cnt;
    }
    // All warps: transpose W_op (j,c) -> s_w4[c][.] feature-first.
    for (int e = tid; e < 67 * 64; e += 128) {
        const int j  = e >> 6;
        const int cc = e & 63;
        const int jp = (j < 3) ? (64 + j) : (j - 3);
        reinterpret_cast<float*>(&s_w4[cc][0])[jp] = W_op[e];
    }
    if (tid < 64) reinterpret_cast<float*>(&s_w4[tid][0])[67] = 0.0f;  // pad slot
    __syncthreads();

    const int cnt0 = s_count[0];
    const int cnt1 = s_count[1];

    // ---- Phase C: gather both centers' neighbors -> s_in4[c2] rows [feat|rel|0] ----
    {
        const int row  = tid >> 1;         // 0..63
        const int c2   = row >> 5;         // center select
        const int k    = row & 31;
        const int part = tid & 1;          // 2 threads per row, 8 float4 each
        const int cnt  = c2 ? cnt1 : cnt0;
        float4 v[8];
        #pragma unroll
        for (int t = 0; t < 8; t++) v[t] = make_float4(0.f, 0.f, 0.f, 0.f);
        float4 relc = make_float4(0.f, 0.f, 0.f, 0.f);
        if (k < cnt) {
            const int idx = s_idx[c2][k];
            const float4* frow =
                reinterpret_cast<const float4*>(features + ((size_t)b * NN + idx) * CC);
            #pragma unroll
            for (int t = 0; t < 8; t++) v[t] = frow[part * 8 + t];
            if (part == 0) {
                const float* p   = positions + ((size_t)b * NN + idx) * 3;
                const float* ctr = centers + (size_t)(m0 + c2) * 3;
                relc.x = p[0] - ctr[0];
                relc.y = p[1] - ctr[1];
                relc.z = p[2] - ctr[2];
            }
        }
        #pragma unroll
        for (int t = 0; t < 8; t++) s_in4[c2][k][part * 8 + t] = v[t];
        if (part == 0) s_in4[c2][k][16] = relc;
    }
    __syncthreads();

    // ---- Phase D: dual-center 4x4 register-tiled micro-GEMM (2 x 32 x 64 x 68) ----
    float acc[2][4][4];
    #pragma unroll
    for (int z = 0; z < 2; z++)
        #pragma unroll
        for (int i = 0; i < 4; i++)
            #pragma unroll
            for (int j = 0; j < 4; j++) acc[z][i][j] = 0.0f;

    #pragma unroll
    for (int q = 0; q < NCHUNK; q++) {
        const float4 w0 = s_w4[c0 + 0][q];   // broadcast in each 8-lane phase
        const float4 w1 = s_w4[c0 + 1][q];
        const float4 w2 = s_w4[c0 + 2][q];
        const float4 w3 = s_w4[c0 + 3][q];
        #pragma unroll
        for (int z = 0; z < 2; z++) {
            #pragma unroll
            for (int i = 0; i < 4; i++) {
                const float4 x = s_in4[z][kt + 8 * i][q];  // conflict-free
                acc[z][i][0] = fmaf(x.w, w0.w, fmaf(x.z, w0.z, fmaf(x.y, w0.y, fmaf(x.x, w0.x, acc[z][i][0]))));
                acc[z][i][1] = fmaf(x.w, w1.w, fmaf(x.z, w1.z, fmaf(x.y, w1.y, fmaf(x.x, w1.x, acc[z][i][1]))));
                acc[z][i][2] = fmaf(x.w, w2.w, fmaf(x.z, w2.z, fmaf(x.y, w2.y, fmaf(x.x, w2.x, acc[z][i][2]))));
                acc[z][i][3] = fmaf(x.w, w3.w, fmaf(x.z, w3.z, fmaf(x.y, w3.y, fmaf(x.x, w3.x, acc[z][i][3]))));
            }
        }
    }

    // ---- Epilogue: bias + validity mask + max-pool (registers, then shfl over kt) ----
    float bias[4];
    #pragma unroll
    for (int j = 0; j < 4; j++) bias[j] = b_op[c0 + j];

    #pragma unroll
    for (int z = 0; z < 2; z++) {
        const int cnt = z ? cnt1 : cnt0;
        float pooled[4];
        #pragma unroll
        for (int j = 0; j < 4; j++) {
            float pm = -INFINITY;
            #pragma unroll
            for (int i = 0; i < 4; i++) {
                const int k = kt + 8 * i;
                const float v = (k < cnt) ? (acc[z][i][j] + bias[j]) : 0.0f; // invalid -> 0
                pm = fmaxf(pm, v);
            }
            pooled[j] = pm;
        }
        #pragma unroll
        for (int off = 4; off > 0; off >>= 1) {
            #pragma unroll
            for (int j = 0; j < 4; j++)
                pooled[j] = fmaxf(pooled[j], __shfl_xor_sync(0xffffffffu, pooled[j], off, 8));
        }
        if (kt == 0) {
            s_pool[z][c0 + 0] = pooled[0];
            s_pool[z][c0 + 1] = pooled[1];
            s_pool[z][c0 + 2] = pooled[2];
            s_pool[z][c0 + 3] = pooled[3];
        }
    }
    __syncthreads();

    // ---- Aggregation GEMM (64 -> 128) + ReLU, W_agg loaded once for both centers ----
    {
        const float bb = b_agg[tid];
        float a0 = bb, a1 = bb;
        #pragma unroll 8
        for (int cc = 0; cc < COP; cc++) {
            const float wv = W_agg[cc * COUT + tid];
            a0 = fmaf(s_pool[0][cc], wv, a0);
            a1 = fmaf(s_pool[1][cc], wv, a1);
        }
        out[(size_t)m0 * COUT + tid]          = fmaxf(a0, 0.0f);
        out[(size_t)(m0 + 1) * COUT + tid]    = fmaxf(a1, 0.0f);
    }
}

extern "C" void kernel_launch(void* const* d_in, const int* in_sizes, int n_in,
                              void* d_out, int out_size)
{
    const float* positions = (const float*)d_in[0];
    const float* features  = (const float*)d_in[1];
    const float* centers   = (const float*)d_in[2];
    const float* distances = (const float*)d_in[3];
    const float* W_op      = (const float*)d_in[4];
    const float* b_op      = (const float*)d_in[5];
    const float* W_agg     = (const float*)d_in[6];
    const float* b_agg     = (const float*)d_in[7];
    float*       out       = (float*)d_out;

    pointnet_sampler_kernel<<<(BB * MM) / 2, 128>>>(
        positions, features, centers, distances,
        W_op, b_op, W_agg, b_agg, out);
}

// round 16
// speedup vs baseline: 1.0054x; 1.0054x over previous
#include <cuda_runtime.h>
#include <math.h>

// Fixed shapes
#define BB     4
#define NN     16384
#define MM     1024
#define CC     64          // feature channels
#define COP    64          // NeighborOperator out channels
#define COUT   128         // final out channels
#define KK     32          // neighbors
#define R2     0.25f
#define NCHUNK 17          // float4 chunks per row: [feat(64) | rel(3) | pad]
// Row layout (68 floats): [feat(64) | rel(3) | 0]. W_op rows reordered to match:
//   W_op row j<3 (rel)   -> slot 64+j
//   W_op row j>=3 (feat) -> slot j-3

__global__ __launch_bounds__(128, 5)
void pointnet_sampler_kernel(
    const float* __restrict__ positions,   // (B, N, 3)
    const float* __restrict__ features,    // (B, N, 64)
    const float* __restrict__ centers,     // (B, M, 3)
    const float* __restrict__ distances,   // (B, M, N)
    const float* __restrict__ W_op,        // (67, 64)
    const float* __restrict__ b_op,        // (64,)
    const float* __restrict__ W_agg,       // (64, 128)
    const float* __restrict__ b_agg,       // (128,)
    float* __restrict__ out)               // (B, M, 128)
{
    const int bm2  = blockIdx.x;           // 0 .. B*M/2-1 : handles centers 2*bm2, 2*bm2+1
    const int m0   = bm2 << 1;             // first center (global index over B*M)
    const int b    = bm2 >> 9;             // batch (both centers share it: M even)
    const int tid  = threadIdx.x;
    const int lane = tid & 31;
    const int wid  = tid >> 5;
    const int kt   = tid & 7;              // k-lane: rows kt, kt+8, kt+16, kt+24
    const int ct   = tid >> 3;             // channel tile: 4ct .. 4ct+3
    const int c0   = ct << 2;

    __shared__ unsigned s_mask[2][8];
    __shared__ int      s_idx[2][KK];
    __shared__ int      s_count[2];
    __shared__ __align__(16) float4 s_in4[2][KK][NCHUNK];  // 17.4 KB
    __shared__ __align__(16) float4 s_w4[COP][NCHUNK];     // 17.4 KB
    __shared__ float    s_pool[2][COP];

    // ---- Phase A: predicate first 256 distances of BOTH centers in one round trip ----
    {
        const float* d0 = distances + (size_t)m0 * NN;
        const float* d1 = d0 + NN;
        const unsigned ma = __ballot_sync(0xffffffffu, d0[tid]       < R2);
        const unsigned mb = __ballot_sync(0xffffffffu, d0[tid + 128] < R2);
        const unsigned mc = __ballot_sync(0xffffffffu, d1[tid]       < R2);
        const unsigned md = __ballot_sync(0xffffffffu, d1[tid + 128] < R2);
        if (lane == 0) {
            s_mask[0][wid]     = ma;  s_mask[0][4 + wid] = mb;
            s_mask[1][wid]     = mc;  s_mask[1][4 + wid] = md;
        }
    }
    __syncthreads();

    // ---- Phase B: warps 0,1 extract first-K indices (center wid); all warps stage W ----
    if (wid < 2) {
        int cnt = 0;
        #pragma unroll
        for (int mm = 0; mm < 8; mm++) {
            const unsigned m = s_mask[wid][mm];
            const bool pred = (m >> lane) & 1u;
            const int rank = cnt + __popc(m & ((1u << lane) - 1u));
            if (pred && rank < KK) s_idx[wid][rank] = mm * 32 + lane;
            cnt += __popc(m);
        }
        // Rare fallback (~1e-6 per row): continue scan past 256 in original order.
        const float* drow = distances + (size_t)(m0 + wid) * NN;
        for (int j0 = 256; j0 < NN && cnt < KK; j0 += 32) {
            const bool pred = drow[j0 + lane] < R2;
            const unsigned m = __ballot_sync(0xffffffffu, pred);
            if (pred) {
                const int rank = cnt + __popc(m & ((1u << lane) - 1u));
                if (rank < KK) s_idx[wid][rank] = j0 + lane;
            }
            cnt += __popc(m);
        }
        if (lane == 0) s_count[wid] = (cnt > KK) ? KK : cnt;
    }
    // All warps: transpose W_op (j,c) -> s_w4[c][.] feature-first.
    for (int e = tid; e < 67 * 64; e += 128) {
        const int j  = e >> 6;
        const int cc = e & 63;
        const int jp = (j < 3) ? (64 + j) : (j - 3);
        reinterpret_cast<float*>(&s_w4[cc][0])[jp] = W_op[e];
    }
    if (tid < 64) reinterpret_cast<float*>(&s_w4[tid][0])[67] = 0.0f;  // pad slot
    __syncthreads();

    const int cnt0 = s_count[0];
    const int cnt1 = s_count[1];

    // ---- Phase C: gather both centers' neighbors -> s_in4[c2] rows [feat|rel|0] ----
    {
        const int row  = tid >> 1;         // 0..63
        const int c2   = row >> 5;         // center select
        const int k    = row & 31;
        const int part = tid & 1;          // 2 threads per row, 8 float4 each
        const int cnt  = c2 ? cnt1 : cnt0;
        float4 v[8];
        #pragma unroll
        for (int t = 0; t < 8; t++) v[t] = make_float4(0.f, 0.f, 0.f, 0.f);
        float4 relc = make_float4(0.f, 0.f, 0.f, 0.f);
        if (k < cnt) {
            const int idx = s_idx[c2][k];
            const float4* frow =
                reinterpret_cast<const float4*>(features + ((size_t)b * NN + idx) * CC);
            #pragma unroll
            for (int t = 0; t < 8; t++) v[t] = frow[part * 8 + t];
            if (part == 0) {
                const float* p   = positions + ((size_t)b * NN + idx) * 3;
                const float* ctr = centers + (size_t)(m0 + c2) * 3;
                relc.x = p[0] - ctr[0];
                relc.y = p[1] - ctr[1];
                relc.z = p[2] - ctr[2];
            }
        }
        #pragma unroll
        for (int t = 0; t < 8; t++) s_in4[c2][k][part * 8 + t] = v[t];
        if (part == 0) s_in4[c2][k][16] = relc;
    }
    __syncthreads();

    // ---- Phase D: dual-center 4x4 register-tiled micro-GEMM (2 x 32 x 64 x 68) ----
    float acc[2][4][4];
    #pragma unroll
    for (int z = 0; z < 2; z++)
        #pragma unroll
        for (int i = 0; i < 4; i++)
            #pragma unroll
            for (int j = 0; j < 4; j++) acc[z][i][j] = 0.0f;

    #pragma unroll
    for (int q = 0; q < NCHUNK; q++) {
        const float4 w0 = s_w4[c0 + 0][q];   // broadcast in each 8-lane phase
        const float4 w1 = s_w4[c0 + 1][q];
        const float4 w2 = s_w4[c0 + 2][q];
        const float4 w3 = s_w4[c0 + 3][q];
        #pragma unroll
        for (int z = 0; z < 2; z++) {
            #pragma unroll
            for (int i = 0; i < 4; i++) {
                const float4 x = s_in4[z][kt + 8 * i][q];  // conflict-free
                acc[z][i][0] = fmaf(x.w, w0.w, fmaf(x.z, w0.z, fmaf(x.y, w0.y, fmaf(x.x, w0.x, acc[z][i][0]))));
                acc[z][i][1] = fmaf(x.w, w1.w, fmaf(x.z, w1.z, fmaf(x.y, w1.y, fmaf(x.x, w1.x, acc[z][i][1]))));
                acc[z][i][2] = fmaf(x.w, w2.w, fmaf(x.z, w2.z, fmaf(x.y, w2.y, fmaf(x.x, w2.x, acc[z][i][2]))));
                acc[z][i][3] = fmaf(x.w, w3.w, fmaf(x.z, w3.z, fmaf(x.y, w3.y, fmaf(x.x, w3.x, acc[z][i][3]))));
            }
        }
    }

    // ---- Epilogue: bias + validity mask + max-pool (registers, then shfl over kt) ----
    float bias[4];
    #pragma unroll
    for (int j = 0; j < 4; j++) bias[j] = b_op[c0 + j];

    #pragma unroll
    for (int z = 0; z < 2; z++) {
        const int cnt = z ? cnt1 : cnt0;
        float pooled[4];
        #pragma unroll
        for (int j = 0; j < 4; j++) {
            float pm = -INFINITY;
            #pragma unroll
            for (int i = 0; i < 4; i++) {
                const int k = kt + 8 * i;
                const float v = (k < cnt) ? (acc[z][i][j] + bias[j]) : 0.0f; // invalid -> 0
                pm = fmaxf(pm, v);
            }
            pooled[j] = pm;
        }
        #pragma unroll
        for (int off = 4; off > 0; off >>= 1) {
            #pragma unroll
            for (int j = 0; j < 4; j++)
                pooled[j] = fmaxf(pooled[j], __shfl_xor_sync(0xffffffffu, pooled[j], off, 8));
        }
        if (kt == 0) {
            s_pool[z][c0 + 0] = pooled[0];
            s_pool[z][c0 + 1] = pooled[1];
            s_pool[z][c0 + 2] = pooled[2];
            s_pool[z][c0 + 3] = pooled[3];
        }
    }
    __syncthreads();

    // ---- Aggregation GEMM (64 -> 128) + ReLU, W_agg loaded once for both centers ----
    {
        const float bb = b_agg[tid];
        float a0 = bb, a1 = bb;
        #pragma unroll 8
        for (int cc = 0; cc < COP; cc++) {
            const float wv = W_agg[cc * COUT + tid];
            a0 = fmaf(s_pool[0][cc], wv, a0);
            a1 = fmaf(s_pool[1][cc], wv, a1);
        }
        out[(size_t)m0 * COUT + tid]          = fmaxf(a0, 0.0f);
        out[(size_t)(m0 + 1) * COUT + tid]    = fmaxf(a1, 0.0f);
    }
}

extern "C" void kernel_launch(void* const* d_in, const int* in_sizes, int n_in,
                              void* d_out, int out_size)
{
    const float* positions = (const float*)d_in[0];
    const float* features  = (const float*)d_in[1];
    const float* centers   = (const float*)d_in[2];
    const float* distances = (const float*)d_in[3];
    const float* W_op      = (const float*)d_in[4];
    const float* b_op      = (const float*)d_in[5];
    const float* W_agg     = (const float*)d_in[6];
    const float* b_agg     = (const float*)d_in[7];
    float*       out       = (float*)d_out;

    pointnet_sampler_kernel<<<(BB * MM) / 2, 128>>>(
        positions, features, centers, distances,
        W_op, b_op, W_agg, b_agg, out);
}

// round 17
// speedup vs baseline: 1.1334x; 1.1273x over previous
#include <cuda_runtime.h>
#include <math.h>

// Fixed shapes
#define NN     16384
#define CC     64          // feature channels
#define COP    64          // NeighborOperator out channels
#define COUT   128         // final out channels
#define KK     32          // neighbors
#define R2     0.25f
#define NCHUNK 17          // float4 chunks per row: [feat(64) | rel(3) | pad]
#define PAIRS  2048        // B*M/2 center pairs
#define GRID   740         // 5 CTAs/SM * 148 SMs: persistent-ish strided loop
// Row layout (68 floats): [feat(64) | rel(3) | 0]. W_op rows reordered to match:
//   W_op row j<3 (rel)   -> slot 64+j ;  row j>=3 (feat) -> slot j-3

__device__ __forceinline__ unsigned smem_u32(const void* p) {
    return (unsigned)__cvta_generic_to_shared(p);
}

__global__ __launch_bounds__(128, 5)
void pointnet_sampler_kernel(
    const float* __restrict__ positions,   // (B, N, 3)
    const float* __restrict__ features,    // (B, N, 64)
    const float* __restrict__ centers,     // (B, M, 3)
    const float* __restrict__ distances,   // (B, M, N)
    const float* __restrict__ W_op,        // (67, 64)
    const float* __restrict__ b_op,        // (64,)
    const float* __restrict__ W_agg,       // (64, 128)
    const float* __restrict__ b_agg,       // (128,)
    float* __restrict__ out)               // (B, M, 128)
{
    const int tid  = threadIdx.x;
    const int lane = tid & 31;
    const int wid  = tid >> 5;
    const int kt   = tid & 7;              // k-lane: rows kt, kt+8, kt+16, kt+24
    const int c0   = (tid >> 3) << 2;      // channels c0 .. c0+3

    __shared__ unsigned s_mask[2][8];
    __shared__ int      s_idx[2][KK];
    __shared__ int      s_count[2];
    __shared__ __align__(16) float4 s_in4[2][KK][NCHUNK];  // 17.4 KB (single pair buffer)
    __shared__ __align__(16) float4 s_w4[COP][NCHUNK];     // 17.4 KB (persistent W)
    __shared__ float    s_pool[2][COP];

    // ---- One-time per CTA: stage W_op transposed, hoist biases ----
    for (int e = tid; e < 67 * 64; e += 128) {
        const int j  = e >> 6;
        const int cc = e & 63;
        const int jp = (j < 3) ? (64 + j) : (j - 3);
        reinterpret_cast<float*>(&s_w4[cc][0])[jp] = W_op[e];
    }
    if (tid < 64) reinterpret_cast<float*>(&s_w4[tid][0])[67] = 0.0f;  // pad slot

    float bias[4];
    #pragma unroll
    for (int j = 0; j < 4; j++) bias[j] = b_op[c0 + j];
    const float bagg = b_agg[tid];

    int p = blockIdx.x;                    // pair index; strided by GRID

    // ---- Prolog: distances + ballot for first pair ----
    float d0a, d0b, d1a, d1b;
    {
        const float* dp = distances + (size_t)(p << 1) * NN;
        d0a = dp[tid];      d0b = dp[tid + 128];
        d1a = dp[NN + tid]; d1b = dp[NN + tid + 128];
    }
    {
        const unsigned ma = __ballot_sync(0xffffffffu, d0a < R2);
        const unsigned mb = __ballot_sync(0xffffffffu, d0b < R2);
        const unsigned mc = __ballot_sync(0xffffffffu, d1a < R2);
        const unsigned md = __ballot_sync(0xffffffffu, d1b < R2);
        if (lane == 0) {
            s_mask[0][wid] = ma;  s_mask[0][4 + wid] = mb;
            s_mask[1][wid] = mc;  s_mask[1][4 + wid] = md;
        }
    }
    __syncthreads();   // W + masks visible

    while (true) {
        const int  m0      = p << 1;
        const int  b       = p >> 9;        // batch (M=1024 centers per batch, pairs share it)
        const int  pn      = p + GRID;
        const bool hasnext = pn < PAIRS;

        // ---- Extract first-K indices for pair p (warps 0,1; masks already in smem) ----
        if (wid < 2) {
            int cnt = 0;
            #pragma unroll
            for (int mm = 0; mm < 8; mm++) {
                const unsigned m = s_mask[wid][mm];
                const bool pred = (m >> lane) & 1u;
                const int rank = cnt + __popc(m & ((1u << lane) - 1u));
                if (pred && rank < KK) s_idx[wid][rank] = mm * 32 + lane;
                cnt += __popc(m);
            }
            // Rare fallback (~1e-6/row): continue scan past 256 in original order.
            const float* drow = distances + (size_t)(m0 + wid) * NN;
            for (int j0 = 256; j0 < NN && cnt < KK; j0 += 32) {
                const bool pred = drow[j0 + lane] < R2;
                const unsigned m = __ballot_sync(0xffffffffu, pred);
                if (pred) {
                    const int rank = cnt + __popc(m & ((1u << lane) - 1u));
                    if (rank < KK) s_idx[wid][rank] = j0 + lane;
                }
                cnt += __popc(m);
            }
            if (cnt > KK) cnt = KK;
            for (int k2 = cnt + lane; k2 < KK; k2 += 32) s_idx[wid][k2] = 0; // safe default
            if (lane == 0) s_count[wid] = cnt;
        }
        __syncthreads();   // (B) idx/count visible

        const int cnt0 = s_count[0];
        const int cnt1 = s_count[1];

        // ---- Gather feats via cp.async; pos LDG; prefetch next pair's distances ----
        {
            const int row  = tid >> 1;       // 0..63: center row>>5, k row&31
            const int c2   = row >> 5;
            const int k    = row & 31;
            const int part = tid & 1;        // 2 threads/row, 8x16B each
            const int idx  = s_idx[c2][k];
            const float* src = features + ((size_t)b * NN + idx) * CC + part * 32;
            const unsigned dst = smem_u32(&s_in4[c2][k][part * 8]);
            #pragma unroll
            for (int t = 0; t < 8; t++)
                asm volatile("cp.async.cg.shared.global [%0], [%1], 16;"
                             :: "r"(dst + t * 16), "l"(src + t * 4));
            asm volatile("cp.async.commit_group;" ::: "memory");
        }
        float rx = 0.f, ry = 0.f, rz = 0.f;
        if (tid < 64) {
            const int c2p = tid >> 5, kp = tid & 31;
            const int idx = s_idx[c2p][kp];
            const float* pp  = positions + ((size_t)b * NN + idx) * 3;
            const float* ctr = centers + (size_t)(m0 + c2p) * 3;
            rx = pp[0] - ctr[0];  ry = pp[1] - ctr[1];  rz = pp[2] - ctr[2];
        }
        if (hasnext) {   // dist for pair pn: latency hidden behind gather wait + GEMM
            const float* dn = distances + (size_t)(pn << 1) * NN;
            d0a = dn[tid];      d0b = dn[tid + 128];
            d1a = dn[NN + tid]; d1b = dn[NN + tid + 128];
        }
        asm volatile("cp.async.wait_group 0;" ::: "memory");
        if (tid < 64) s_in4[tid >> 5][tid & 31][16] = make_float4(rx, ry, rz, 0.f);
        __syncthreads();   // (C) s_in4 fully ready

        // ---- Dual-center 4x4 register-tiled micro-GEMM (2 x 32 x 64 x 68) ----
        float acc[2][4][4];
        #pragma unroll
        for (int z = 0; z < 2; z++)
            #pragma unroll
            for (int i = 0; i < 4; i++)
                #pragma unroll
                for (int j = 0; j < 4; j++) acc[z][i][j] = 0.0f;

        #pragma unroll
        for (int q = 0; q < NCHUNK; q++) {
            const float4 w0 = s_w4[c0 + 0][q];   // broadcast within 8-lane phase
            const float4 w1 = s_w4[c0 + 1][q];
            const float4 w2 = s_w4[c0 + 2][q];
            const float4 w3 = s_w4[c0 + 3][q];
            #pragma unroll
            for (int z = 0; z < 2; z++) {
                #pragma unroll
                for (int i = 0; i < 4; i++) {
                    const float4 x = s_in4[z][kt + 8 * i][q];  // conflict-free banks
                    acc[z][i][0] = fmaf(x.w, w0.w, fmaf(x.z, w0.z, fmaf(x.y, w0.y, fmaf(x.x, w0.x, acc[z][i][0]))));
                    acc[z][i][1] = fmaf(x.w, w1.w, fmaf(x.z, w1.z, fmaf(x.y, w1.y, fmaf(x.x, w1.x, acc[z][i][1]))));
                    acc[z][i][2] = fmaf(x.w, w2.w, fmaf(x.z, w2.z, fmaf(x.y, w2.y, fmaf(x.x, w2.x, acc[z][i][2]))));
                    acc[z][i][3] = fmaf(x.w, w3.w, fmaf(x.z, w3.z, fmaf(x.y, w3.y, fmaf(x.x, w3.x, acc[z][i][3]))));
                }
            }
        }

        // ---- Pool (bias + validity mask + shfl over kt lanes) ----
        #pragma unroll
        for (int z = 0; z < 2; z++) {
            const int cnt = z ? cnt1 : cnt0;
            float pooled[4];
            #pragma unroll
            for (int j = 0; j < 4; j++) {
                float pm = -INFINITY;
                #pragma unroll
                for (int i = 0; i < 4; i++) {
                    const int k = kt + 8 * i;
                    const float v = (k < cnt) ? (acc[z][i][j] + bias[j]) : 0.0f;
                    pm = fmaxf(pm, v);
                }
                pooled[j] = pm;
            }
            #pragma unroll
            for (int off = 4; off > 0; off >>= 1) {
                #pragma unroll
                for (int j = 0; j < 4; j++)
                    pooled[j] = fmaxf(pooled[j], __shfl_xor_sync(0xffffffffu, pooled[j], off, 8));
            }
            if (kt == 0) {
                s_pool[z][c0 + 0] = pooled[0];
                s_pool[z][c0 + 1] = pooled[1];
                s_pool[z][c0 + 2] = pooled[2];
                s_pool[z][c0 + 3] = pooled[3];
            }
        }

        // ---- Ballot for next pair (dist regs arrived during GEMM) ----
        if (hasnext) {
            const unsigned ma = __ballot_sync(0xffffffffu, d0a < R2);
            const unsigned mb = __ballot_sync(0xffffffffu, d0b < R2);
            const unsigned mc = __ballot_sync(0xffffffffu, d1a < R2);
            const unsigned md = __ballot_sync(0xffffffffu, d1b < R2);
            if (lane == 0) {
                s_mask[0][wid] = ma;  s_mask[0][4 + wid] = mb;
                s_mask[1][wid] = mc;  s_mask[1][4 + wid] = md;
            }
        }
        __syncthreads();   // (D/A merged) pool + next masks visible

        // ---- Aggregation GEMM (64 -> 128) + ReLU, shared W_agg loads ----
        {
            float a0 = bagg, a1 = bagg;
            #pragma unroll 8
            for (int cc = 0; cc < COP; cc++) {
                const float wv = W_agg[cc * COUT + tid];
                a0 = fmaf(s_pool[0][cc], wv, a0);
                a1 = fmaf(s_pool[1][cc], wv, a1);
            }
            out[(size_t)m0 * COUT + tid]       = fmaxf(a0, 0.0f);
            out[(size_t)(m0 + 1) * COUT + tid] = fmaxf(a1, 0.0f);
        }

        if (!hasnext) break;
        p = pn;
    }
}

extern "C" void kernel_launch(void* const* d_in, const int* in_sizes, int n_in,
                              void* d_out, int out_size)
{
    const float* positions = (const float*)d_in[0];
    const float* features  = (const float*)d_in[1];
    const float* centers   = (const float*)d_in[2];
    const float* distances = (const float*)d_in[3];
    const float* W_op      = (const float*)d_in[4];
    const float* b_op      = (const float*)d_in[5];
    const float* W_agg     = (const float*)d_in[6];
    const float* b_agg     = (const float*)d_in[7];
    float*       out       = (float*)d_out;

    pointnet_sampler_kernel<<<GRID, 128>>>(
        positions, features, centers, distances,
        W_op, b_op, W_agg, b_agg, out);
}